// round 5
// baseline (speedup 1.0000x reference)
#include <cuda_runtime.h>
#include <cuda_fp16.h>
#include <cstdint>

// ============================================================
// Problem constants
// ============================================================
#define BB 2
#define SS 2048
#define DD 1536
#define HH 12
#define HD 128
#define KK 1536                 // GEMM K (plain fp16, no split)
#define MM 4096                 // BB * SS
#define OUT1_ELEMS (MM * DD)    // 6291456
#define ATTN_ELEMS (BB * HH * SS * SS)  // 100663296
#define QCH 256                 // q-chunk for prefix scan
#define NCH (SS / QCH)          // 8 chunks

// GEMM tiling
#define BM 128
#define BN 128
#define BK 32
#define STG 4
#define ROWB 80                  // smem row stride in bytes -- conflict-free ldmatrix
#define TILEB (128 * ROWB)       // 10240 bytes per A or B tile
#define STAGEB (2 * TILEB)       // 20480 bytes per stage
#define GEMM_SMEM (STG * STAGEB) // 81920

// ============================================================
// Scratch (__device__ globals -- no allocation allowed)
// ============================================================
__device__ __half g_Xs[(size_t)MM * KK];   // fp16(hidden)
__device__ __half g_As[(size_t)MM * KK];   // fp16(attn out)
__device__ __half g_Ws1[(size_t)DD * KK];  // fp16(W_fc)
__device__ __half g_Ws2[(size_t)DD * KK];  // fp16(W_proj)
__device__ float  g_V[(size_t)MM * DD];    // fc output (value states)
__device__ float  g_P[(size_t)BB * HH * SS * HD];       // per-chunk local prefix
__device__ float  g_Ct[(size_t)BB * HH * NCH * HD];     // chunk totals

// ============================================================
// PTX helpers (sm_80-era instructions only: valid on compute_103)
// ============================================================
__device__ __forceinline__ uint32_t smem_to_u32(const void* p) {
    uint32_t a;
    asm("{ .reg .u64 t; cvta.to.shared.u64 t, %1; cvt.u32.u64 %0, t; }"
        : "=r"(a) : "l"(p));
    return a;
}

#define CP16(smem_u32, gptr) \
    asm volatile("cp.async.cg.shared.global [%0], [%1], 16;" \
        :: "r"(smem_u32), "l"(gptr))

#define CP_COMMIT() asm volatile("cp.async.commit_group;" ::: "memory")
#define CP_WAIT(n)  asm volatile("cp.async.wait_group %0;" :: "n"(n) : "memory")

__device__ __forceinline__ void ldsm_x4(uint32_t& r0, uint32_t& r1,
                                        uint32_t& r2, uint32_t& r3,
                                        uint32_t addr) {
    asm volatile("ldmatrix.sync.aligned.m8n8.x4.shared.b16 {%0,%1,%2,%3}, [%4];"
                 : "=r"(r0), "=r"(r1), "=r"(r2), "=r"(r3) : "r"(addr));
}

__device__ __forceinline__ void mma16816(float* c, const uint32_t* a,
                                         const uint32_t* b) {
    asm volatile(
        "mma.sync.aligned.m16n8k16.row.col.f32.f16.f16.f32 "
        "{%0,%1,%2,%3}, {%4,%5,%6,%7}, {%8,%9}, {%0,%1,%2,%3};"
        : "+f"(c[0]), "+f"(c[1]), "+f"(c[2]), "+f"(c[3])
        : "r"(a[0]), "r"(a[1]), "r"(a[2]), "r"(a[3]), "r"(b[0]), "r"(b[1]));
}

// ============================================================
// Kernel 1: fp32 -> fp16 convert (4 elements / thread)
// ============================================================
__global__ void __launch_bounds__(256)
cvt_kernel(const float4* __restrict__ src, uint2* __restrict__ dst, int n4) {
    int i = blockIdx.x * 256 + threadIdx.x;
    if (i >= n4) return;
    float4 v = src[i];
    __half2 p0 = __halves2half2(__float2half_rn(v.x), __float2half_rn(v.y));
    __half2 p1 = __halves2half2(__float2half_rn(v.z), __float2half_rn(v.w));
    uint2 o;
    o.x = *reinterpret_cast<uint32_t*>(&p0);
    o.y = *reinterpret_cast<uint32_t*>(&p1);
    dst[i] = o;
}

// ============================================================
// Kernel 2: fp16 mma.sync GEMM  C[M,1536] = A[M,KK] * B[1536,KK]^T + bias
// 128x128x32 CTA tile, 8 warps (2x4), 64x32 warp tile, 4-stage cp.async.
// ============================================================
__global__ void __launch_bounds__(256, 2)
gemm_fp16(const __half* __restrict__ A, const __half* __restrict__ Bw,
          float* __restrict__ C, const float* __restrict__ bias) {
    extern __shared__ char smem[];
    const uint32_t sb = smem_to_u32(smem);
    const int tid = threadIdx.x;
    const int lane = tid & 31;
    const int warp = tid >> 5;
    const int warpM = warp >> 2;   // 0..1 (64 rows each)
    const int warpN = warp & 3;    // 0..3 (32 cols each)

    const int ldRow = tid >> 1;
    const int ldCol = (tid & 1) * 2;
    const __half* gA = A + ((size_t)blockIdx.y * BM + ldRow) * KK + ldCol * 8;
    const __half* gB = Bw + ((size_t)blockIdx.x * BN + ldRow) * KK + ldCol * 8;
    const uint32_t stOff = (uint32_t)ldRow * ROWB + (uint32_t)ldCol * 16;

    const int aRow = (lane & 7) + ((lane >> 3) & 1) * 8;
    const uint32_t aBase = sb + (uint32_t)(warpM * 64 + aRow) * ROWB
                              + (uint32_t)(lane >> 4) * 16;
    const int bRow = (lane & 7) + ((lane >> 4) & 1) * 8;
    const uint32_t bBase = sb + TILEB + (uint32_t)(warpN * 32 + bRow) * ROWB
                              + (uint32_t)((lane >> 3) & 1) * 16;

    float acc[4][4][4];
#pragma unroll
    for (int i = 0; i < 4; ++i)
#pragma unroll
        for (int j = 0; j < 4; ++j)
#pragma unroll
            for (int k = 0; k < 4; ++k) acc[i][j][k] = 0.0f;

    const int NIT = KK / BK;  // 48

#pragma unroll
    for (int s = 0; s < STG - 1; ++s) {
        const uint32_t base = sb + s * STAGEB;
        const __half* ga = gA + s * BK;
        const __half* gb = gB + s * BK;
        CP16(base + stOff, ga);
        CP16(base + stOff + 16, ga + 8);
        CP16(base + TILEB + stOff, gb);
        CP16(base + TILEB + stOff + 16, gb + 8);
        CP_COMMIT();
    }

    for (int it = 0; it < NIT; ++it) {
        CP_WAIT(STG - 2);
        __syncthreads();

        const int pf = it + STG - 1;
        if (pf < NIT) {
            const uint32_t base = sb + (pf & (STG - 1)) * STAGEB;
            const __half* ga = gA + pf * BK;
            const __half* gb = gB + pf * BK;
            CP16(base + stOff, ga);
            CP16(base + stOff + 16, ga + 8);
            CP16(base + TILEB + stOff, gb);
            CP16(base + TILEB + stOff + 16, gb + 8);
        }
        CP_COMMIT();

        const uint32_t soff = (it & (STG - 1)) * STAGEB;
#pragma unroll
        for (int kk = 0; kk < 2; ++kk) {
            uint32_t a[4][4];
            uint32_t b[4][2];
#pragma unroll
            for (int mt = 0; mt < 4; ++mt)
                ldsm_x4(a[mt][0], a[mt][1], a[mt][2], a[mt][3],
                        aBase + soff + (uint32_t)mt * (16 * ROWB) + kk * 32);
            ldsm_x4(b[0][0], b[0][1], b[1][0], b[1][1],
                    bBase + soff + kk * 32);
            ldsm_x4(b[2][0], b[2][1], b[3][0], b[3][1],
                    bBase + soff + (16 * ROWB) + kk * 32);
#pragma unroll
            for (int mt = 0; mt < 4; ++mt)
#pragma unroll
                for (int nt = 0; nt < 4; ++nt)
                    mma16816(acc[mt][nt], a[mt], b[nt]);
        }
    }

    const int r0 = blockIdx.y * BM + warpM * 64 + (lane >> 2);
    const int c0 = blockIdx.x * BN + warpN * 32 + (lane & 3) * 2;
#pragma unroll
    for (int nt = 0; nt < 4; ++nt) {
        const int col = c0 + nt * 8;
        const float bx = bias[col], by = bias[col + 1];
#pragma unroll
        for (int mt = 0; mt < 4; ++mt) {
            const int row = r0 + mt * 16;
            float2 v0 = make_float2(acc[mt][nt][0] + bx, acc[mt][nt][1] + by);
            float2 v1 = make_float2(acc[mt][nt][2] + bx, acc[mt][nt][3] + by);
            *reinterpret_cast<float2*>(C + (size_t)row * DD + col) = v0;
            *reinterpret_cast<float2*>(C + (size_t)(row + 8) * DD + col) = v1;
        }
    }
}

// ============================================================
// Kernel 3a: per-chunk local prefix scan along q.
// Grid: B*H*NCH = 192 CTAs, 128 threads (one per head-dim d).
// ============================================================
__global__ void __launch_bounds__(128)
scan_kernel() {
    const int bhc = blockIdx.x;
    const int c = bhc & (NCH - 1);
    const int h = (bhc >> 3) % HH;
    const int b = bhc / (HH * NCH);
    const int d = threadIdx.x;

    const float* vp = g_V + ((size_t)b * SS + c * QCH) * DD + h * HD + d;
    float* pp = g_P + (((size_t)(b * HH + h) * SS) + c * QCH) * HD + d;

    float acc = 0.0f;
#pragma unroll 8
    for (int i = 0; i < QCH; ++i) {
        acc += vp[(size_t)i * DD];
        pp[(size_t)i * HD] = acc;
    }
    g_Ct[((size_t)(b * HH + h) * NCH + c) * HD + d] = acc;
}

// ============================================================
// Kernel 3b: window-mean from prefix sums -> fp16 into g_As.
// Grid: B*H*NCH = 192 CTAs, 128 threads (d).
// out[q,d] = (P[q] - P[q-w]) / len   (len = min(q+1, w))
// ============================================================
__global__ void __launch_bounds__(128)
attn_out_kernel() {
    const int bhc = blockIdx.x;
    const int c = bhc & (NCH - 1);
    const int h = (bhc >> 3) % HH;
    const int b = bhc / (HH * NCH);
    const int d = threadIdx.x;
    const int w = (1 << (h + 1)) - 1;
    const int q0 = c * QCH;
    const int c2a = (q0 - w) >> 8;       // arithmetic shift; may be negative

    const float* ct = g_Ct + (size_t)(b * HH + h) * NCH * HD + d;
    float run = 0.0f, offc = 0.0f, offA = 0.0f, offB = 0.0f;
#pragma unroll
    for (int cc = 0; cc < NCH; ++cc) {
        if (cc == c)       offc = run;
        if (cc == c2a)     offA = run;
        if (cc == c2a + 1) offB = run;
        run += ct[(size_t)cc * HD];
    }

    const float* Pb = g_P + (size_t)(b * HH + h) * SS * HD + d;
    __half* op = g_As + ((size_t)b * SS + q0) * KK + (size_t)h * HD + d;
    const float invw = 1.0f / (float)w;

#pragma unroll 4
    for (int i = 0; i < QCH; ++i) {
        const int q = q0 + i;
        const float Pq = Pb[(size_t)q * HD] + offc;
        const int q2 = q - w;
        float prev, inv;
        if (q2 >= 0) {
            const int cc2 = q2 >> 8;
            const float off2 = (cc2 == c2a) ? offA : offB;
            prev = Pb[(size_t)q2 * HD] + off2;
            inv = invw;
        } else {
            prev = 0.0f;
            inv = 1.0f / (float)(q + 1);
        }
        op[(size_t)i * KK] = __float2half_rn((Pq - prev) * inv);
    }
}

// ============================================================
// Kernel 4: dense attn_weights pattern writer [B,H,S,S]
// ============================================================
__global__ void __launch_bounds__(256)
attnw_kernel(float* __restrict__ out2) {
    const int row = blockIdx.x;          // ((b*H + h)*S + q)
    const int q = row & (SS - 1);
    const int h = (row >> 11) % HH;
    const int w = (1 << (h + 1)) - 1;
    const int lo = q - w + 1;
    const int len = (q + 1 < w) ? (q + 1) : w;
    const float inv = 1.0f / (float)len;

    float* p = out2 + (size_t)row * SS;
    const int k0 = threadIdx.x * 8;
    float4 v0, v1;
    {
        int k;
        k = k0 + 0; v0.x = (k <= q && k >= lo) ? inv : 0.0f;
        k = k0 + 1; v0.y = (k <= q && k >= lo) ? inv : 0.0f;
        k = k0 + 2; v0.z = (k <= q && k >= lo) ? inv : 0.0f;
        k = k0 + 3; v0.w = (k <= q && k >= lo) ? inv : 0.0f;
        k = k0 + 4; v1.x = (k <= q && k >= lo) ? inv : 0.0f;
        k = k0 + 5; v1.y = (k <= q && k >= lo) ? inv : 0.0f;
        k = k0 + 6; v1.z = (k <= q && k >= lo) ? inv : 0.0f;
        k = k0 + 7; v1.w = (k <= q && k >= lo) ? inv : 0.0f;
    }
    *reinterpret_cast<float4*>(p + k0)     = v0;
    *reinterpret_cast<float4*>(p + k0 + 4) = v1;
}

// ============================================================
// Host launcher -- fork-join dual-stream graph
// ============================================================
extern "C" void kernel_launch(void* const* d_in, const int* in_sizes, int n_in,
                              void* d_out, int out_size) {
    const float* hs  = (const float*)d_in[0];
    const float* Wfc = (const float*)d_in[1];
    const float* bfc = (const float*)d_in[2];
    const float* Wpj = (const float*)d_in[3];
    const float* bpj = (const float*)d_in[4];
    float* out = (float*)d_out;

    void *pXs, *pAs, *pWs1, *pWs2, *pV;
    cudaGetSymbolAddress(&pXs,  g_Xs);
    cudaGetSymbolAddress(&pAs,  g_As);
    cudaGetSymbolAddress(&pWs1, g_Ws1);
    cudaGetSymbolAddress(&pWs2, g_Ws2);
    cudaGetSymbolAddress(&pV,   g_V);

    cudaFuncSetAttribute(gemm_fp16,
                         cudaFuncAttributeMaxDynamicSharedMemorySize, GEMM_SMEM);

    // Fork-join side stream. kernel_launch is only invoked a handful of times
    // (correctness + capture), so per-call creation without destroy is a
    // bounded host-side leak; no device memory is involved.
    cudaStream_t sB;
    cudaStreamCreateWithFlags(&sB, cudaStreamNonBlocking);
    cudaEvent_t evF, evJ;
    cudaEventCreateWithFlags(&evF, cudaEventDisableTiming);
    cudaEventCreateWithFlags(&evJ, cudaEventDisableTiming);

    // ---- fork ----
    cudaEventRecord(evF, 0);
    cudaStreamWaitEvent(sB, evF, 0);

    // ---- stream B: fully independent work (attn_weights + W_proj convert) ----
    long long need = (long long)OUT1_ELEMS + (long long)ATTN_ELEMS;
    if ((long long)out_size >= need) {
        attnw_kernel<<<BB * HH * SS, 256, 0, sB>>>(out + OUT1_ELEMS);
    }
    cvt_kernel<<<(DD * DD / 4 + 255) / 256, 256, 0, sB>>>(
        (const float4*)Wpj, (uint2*)pWs2, DD * DD / 4);

    // ---- main chain (default stream) ----
    cvt_kernel<<<(OUT1_ELEMS / 4 + 255) / 256, 256>>>(
        (const float4*)hs, (uint2*)pXs, OUT1_ELEMS / 4);
    cvt_kernel<<<(DD * DD / 4 + 255) / 256, 256>>>(
        (const float4*)Wfc, (uint2*)pWs1, DD * DD / 4);

    gemm_fp16<<<dim3(DD / BN, MM / BM), 256, GEMM_SMEM>>>(
        (const __half*)pXs, (const __half*)pWs1, (float*)pV, bfc);

    scan_kernel<<<BB * HH * NCH, 128>>>();
    attn_out_kernel<<<BB * HH * NCH, 128>>>();

    gemm_fp16<<<dim3(DD / BN, MM / BM), 256, GEMM_SMEM>>>(
        (const __half*)pAs, (const __half*)pWs2, out, bpj);

    // ---- join ----
    cudaEventRecord(evJ, sB);
    cudaStreamWaitEvent(0, evJ, 0);
}

// round 6
// speedup vs baseline: 1.0578x; 1.0578x over previous
#include <cuda_runtime.h>
#include <cuda_fp16.h>
#include <cstdint>

// ============================================================
// Problem constants
// ============================================================
#define BB 2
#define SS 2048
#define DD 1536
#define HH 12
#define HD 128
#define KK 1536                 // GEMM K (plain fp16)
#define MM 4096                 // BB * SS
#define OUT1_ELEMS (MM * DD)    // 6291456
#define ATTN_ELEMS (BB * HH * SS * SS)  // 100663296
#define NROWS (BB * HH * SS)    // 49152 attn_weights rows
#define QCH 256                 // q-chunk for prefix scan
#define NCH (SS / QCH)          // 8 chunks

// GEMM tiling
#define BM 128
#define BN 128
#define BK 32
#define STG 4
#define ROWB 80                  // smem row stride in bytes -- conflict-free ldmatrix
#define TILEB (128 * ROWB)       // 10240 bytes per A or B tile
#define STAGEB (2 * TILEB)       // 20480 bytes per stage
#define GEMM_SMEM (STG * STAGEB) // 81920

// attn_weights writer: small persistent grid so it CO-RESIDES with the GEMM
#define AWBLK 1184               // 8 CTAs/SM

// ============================================================
// Scratch (__device__ globals -- no allocation allowed)
// ============================================================
__device__ __half g_Xs[(size_t)MM * KK];   // fp16(hidden)
__device__ __half g_As[(size_t)MM * KK];   // fp16(attn out)
__device__ __half g_Ws1[(size_t)DD * KK];  // fp16(W_fc)
__device__ __half g_Ws2[(size_t)DD * KK];  // fp16(W_proj)
__device__ float  g_V[(size_t)MM * DD];    // fc output (value states)
__device__ float  g_P[(size_t)BB * HH * SS * HD];       // per-chunk local prefix
__device__ float  g_Ct[(size_t)BB * HH * NCH * HD];     // chunk totals

// ============================================================
// PTX helpers (sm_80-era instructions only: valid on compute_103)
// ============================================================
__device__ __forceinline__ uint32_t smem_to_u32(const void* p) {
    uint32_t a;
    asm("{ .reg .u64 t; cvta.to.shared.u64 t, %1; cvt.u32.u64 %0, t; }"
        : "=r"(a) : "l"(p));
    return a;
}

#define CP16(smem_u32, gptr) \
    asm volatile("cp.async.cg.shared.global [%0], [%1], 16;" \
        :: "r"(smem_u32), "l"(gptr))

#define CP_COMMIT() asm volatile("cp.async.commit_group;" ::: "memory")
#define CP_WAIT(n)  asm volatile("cp.async.wait_group %0;" :: "n"(n) : "memory")

__device__ __forceinline__ void ldsm_x4(uint32_t& r0, uint32_t& r1,
                                        uint32_t& r2, uint32_t& r3,
                                        uint32_t addr) {
    asm volatile("ldmatrix.sync.aligned.m8n8.x4.shared.b16 {%0,%1,%2,%3}, [%4];"
                 : "=r"(r0), "=r"(r1), "=r"(r2), "=r"(r3) : "r"(addr));
}

__device__ __forceinline__ void mma16816(float* c, const uint32_t* a,
                                         const uint32_t* b) {
    asm volatile(
        "mma.sync.aligned.m16n8k16.row.col.f32.f16.f16.f32 "
        "{%0,%1,%2,%3}, {%4,%5,%6,%7}, {%8,%9}, {%0,%1,%2,%3};"
        : "+f"(c[0]), "+f"(c[1]), "+f"(c[2]), "+f"(c[3])
        : "r"(a[0]), "r"(a[1]), "r"(a[2]), "r"(a[3]), "r"(b[0]), "r"(b[1]));
}

// ============================================================
// Kernel 1: fp32 -> fp16 convert (4 elements / thread)
// ============================================================
__global__ void __launch_bounds__(256)
cvt_kernel(const float4* __restrict__ src, uint2* __restrict__ dst, int n4) {
    int i = blockIdx.x * 256 + threadIdx.x;
    if (i >= n4) return;
    float4 v = src[i];
    __half2 p0 = __halves2half2(__float2half_rn(v.x), __float2half_rn(v.y));
    __half2 p1 = __halves2half2(__float2half_rn(v.z), __float2half_rn(v.w));
    uint2 o;
    o.x = *reinterpret_cast<uint32_t*>(&p0);
    o.y = *reinterpret_cast<uint32_t*>(&p1);
    dst[i] = o;
}

// ============================================================
// Kernel 2: fp16 mma.sync GEMM  C[M,1536] = A[M,KK] * B[1536,KK]^T + bias
// 128x128x32 CTA tile, 8 warps (2x4), 64x32 warp tile, 4-stage cp.async.
// ============================================================
__global__ void __launch_bounds__(256, 2)
gemm_fp16(const __half* __restrict__ A, const __half* __restrict__ Bw,
          float* __restrict__ C, const float* __restrict__ bias) {
    extern __shared__ char smem[];
    const uint32_t sb = smem_to_u32(smem);
    const int tid = threadIdx.x;
    const int lane = tid & 31;
    const int warp = tid >> 5;
    const int warpM = warp >> 2;   // 0..1 (64 rows each)
    const int warpN = warp & 3;    // 0..3 (32 cols each)

    const int ldRow = tid >> 1;
    const int ldCol = (tid & 1) * 2;
    const __half* gA = A + ((size_t)blockIdx.y * BM + ldRow) * KK + ldCol * 8;
    const __half* gB = Bw + ((size_t)blockIdx.x * BN + ldRow) * KK + ldCol * 8;
    const uint32_t stOff = (uint32_t)ldRow * ROWB + (uint32_t)ldCol * 16;

    const int aRow = (lane & 7) + ((lane >> 3) & 1) * 8;
    const uint32_t aBase = sb + (uint32_t)(warpM * 64 + aRow) * ROWB
                              + (uint32_t)(lane >> 4) * 16;
    const int bRow = (lane & 7) + ((lane >> 4) & 1) * 8;
    const uint32_t bBase = sb + TILEB + (uint32_t)(warpN * 32 + bRow) * ROWB
                              + (uint32_t)((lane >> 3) & 1) * 16;

    float acc[4][4][4];
#pragma unroll
    for (int i = 0; i < 4; ++i)
#pragma unroll
        for (int j = 0; j < 4; ++j)
#pragma unroll
            for (int k = 0; k < 4; ++k) acc[i][j][k] = 0.0f;

    const int NIT = KK / BK;  // 48

#pragma unroll
    for (int s = 0; s < STG - 1; ++s) {
        const uint32_t base = sb + s * STAGEB;
        const __half* ga = gA + s * BK;
        const __half* gb = gB + s * BK;
        CP16(base + stOff, ga);
        CP16(base + stOff + 16, ga + 8);
        CP16(base + TILEB + stOff, gb);
        CP16(base + TILEB + stOff + 16, gb + 8);
        CP_COMMIT();
    }

    for (int it = 0; it < NIT; ++it) {
        CP_WAIT(STG - 2);
        __syncthreads();

        const int pf = it + STG - 1;
        if (pf < NIT) {
            const uint32_t base = sb + (pf & (STG - 1)) * STAGEB;
            const __half* ga = gA + pf * BK;
            const __half* gb = gB + pf * BK;
            CP16(base + stOff, ga);
            CP16(base + stOff + 16, ga + 8);
            CP16(base + TILEB + stOff, gb);
            CP16(base + TILEB + stOff + 16, gb + 8);
        }
        CP_COMMIT();

        const uint32_t soff = (it & (STG - 1)) * STAGEB;
#pragma unroll
        for (int kk = 0; kk < 2; ++kk) {
            uint32_t a[4][4];
            uint32_t b[4][2];
#pragma unroll
            for (int mt = 0; mt < 4; ++mt)
                ldsm_x4(a[mt][0], a[mt][1], a[mt][2], a[mt][3],
                        aBase + soff + (uint32_t)mt * (16 * ROWB) + kk * 32);
            ldsm_x4(b[0][0], b[0][1], b[1][0], b[1][1],
                    bBase + soff + kk * 32);
            ldsm_x4(b[2][0], b[2][1], b[3][0], b[3][1],
                    bBase + soff + (16 * ROWB) + kk * 32);
#pragma unroll
            for (int mt = 0; mt < 4; ++mt)
#pragma unroll
                for (int nt = 0; nt < 4; ++nt)
                    mma16816(acc[mt][nt], a[mt], b[nt]);
        }
    }

    const int r0 = blockIdx.y * BM + warpM * 64 + (lane >> 2);
    const int c0 = blockIdx.x * BN + warpN * 32 + (lane & 3) * 2;
#pragma unroll
    for (int nt = 0; nt < 4; ++nt) {
        const int col = c0 + nt * 8;
        const float bx = bias[col], by = bias[col + 1];
#pragma unroll
        for (int mt = 0; mt < 4; ++mt) {
            const int row = r0 + mt * 16;
            float2 v0 = make_float2(acc[mt][nt][0] + bx, acc[mt][nt][1] + by);
            float2 v1 = make_float2(acc[mt][nt][2] + bx, acc[mt][nt][3] + by);
            *reinterpret_cast<float2*>(C + (size_t)row * DD + col) = v0;
            *reinterpret_cast<float2*>(C + (size_t)(row + 8) * DD + col) = v1;
        }
    }
}

// ============================================================
// Kernel 3a: per-chunk local prefix scan along q.
// ============================================================
__global__ void __launch_bounds__(128)
scan_kernel() {
    const int bhc = blockIdx.x;
    const int c = bhc & (NCH - 1);
    const int h = (bhc >> 3) % HH;
    const int b = bhc / (HH * NCH);
    const int d = threadIdx.x;

    const float* vp = g_V + ((size_t)b * SS + c * QCH) * DD + h * HD + d;
    float* pp = g_P + (((size_t)(b * HH + h) * SS) + c * QCH) * HD + d;

    float acc = 0.0f;
#pragma unroll 8
    for (int i = 0; i < QCH; ++i) {
        acc += vp[(size_t)i * DD];
        pp[(size_t)i * HD] = acc;
    }
    g_Ct[((size_t)(b * HH + h) * NCH + c) * HD + d] = acc;
}

// ============================================================
// Kernel 3b: window-mean from prefix sums -> fp16 into g_As.
// ============================================================
__global__ void __launch_bounds__(128)
attn_out_kernel() {
    const int bhc = blockIdx.x;
    const int c = bhc & (NCH - 1);
    const int h = (bhc >> 3) % HH;
    const int b = bhc / (HH * NCH);
    const int d = threadIdx.x;
    const int w = (1 << (h + 1)) - 1;
    const int q0 = c * QCH;
    const int c2a = (q0 - w) >> 8;       // arithmetic shift; may be negative

    const float* ct = g_Ct + (size_t)(b * HH + h) * NCH * HD + d;
    float run = 0.0f, offc = 0.0f, offA = 0.0f, offB = 0.0f;
#pragma unroll
    for (int cc = 0; cc < NCH; ++cc) {
        if (cc == c)       offc = run;
        if (cc == c2a)     offA = run;
        if (cc == c2a + 1) offB = run;
        run += ct[(size_t)cc * HD];
    }

    const float* Pb = g_P + (size_t)(b * HH + h) * SS * HD + d;
    __half* op = g_As + ((size_t)b * SS + q0) * KK + (size_t)h * HD + d;
    const float invw = 1.0f / (float)w;

#pragma unroll 4
    for (int i = 0; i < QCH; ++i) {
        const int q = q0 + i;
        const float Pq = Pb[(size_t)q * HD] + offc;
        const int q2 = q - w;
        float prev, inv;
        if (q2 >= 0) {
            const int cc2 = q2 >> 8;
            const float off2 = (cc2 == c2a) ? offA : offB;
            prev = Pb[(size_t)q2 * HD] + off2;
            inv = invw;
        } else {
            prev = 0.0f;
            inv = 1.0f / (float)(q + 1);
        }
        op[(size_t)i * KK] = __float2half_rn((Pq - prev) * inv);
    }
}

// ============================================================
// Kernel 4: dense attn_weights pattern writer [B,H,S,S]
// Persistent grid-stride (AWBLK CTAs, ~8/SM) + streaming stores so it
// co-resides with the GEMM chain instead of monopolizing the chip.
// ============================================================
__global__ void __launch_bounds__(256)
attnw_kernel(float* __restrict__ out2) {
    const int k0 = threadIdx.x * 8;
    for (int row = blockIdx.x; row < NROWS; row += AWBLK) {
        const int q = row & (SS - 1);
        const int h = (row >> 11) % HH;
        const int w = (1 << (h + 1)) - 1;
        const int lo = q - w + 1;
        const int len = (q + 1 < w) ? (q + 1) : w;
        const float inv = 1.0f / (float)len;

        float* p = out2 + (size_t)row * SS;
        float4 v0, v1;
        int k;
        k = k0 + 0; v0.x = (k <= q && k >= lo) ? inv : 0.0f;
        k = k0 + 1; v0.y = (k <= q && k >= lo) ? inv : 0.0f;
        k = k0 + 2; v0.z = (k <= q && k >= lo) ? inv : 0.0f;
        k = k0 + 3; v0.w = (k <= q && k >= lo) ? inv : 0.0f;
        k = k0 + 4; v1.x = (k <= q && k >= lo) ? inv : 0.0f;
        k = k0 + 5; v1.y = (k <= q && k >= lo) ? inv : 0.0f;
        k = k0 + 6; v1.z = (k <= q && k >= lo) ? inv : 0.0f;
        k = k0 + 7; v1.w = (k <= q && k >= lo) ? inv : 0.0f;
        __stcs(reinterpret_cast<float4*>(p + k0), v0);
        __stcs(reinterpret_cast<float4*>(p + k0 + 4), v1);
    }
}

// ============================================================
// Host launcher -- fork-join dual-stream graph with proper deps
// ============================================================
extern "C" void kernel_launch(void* const* d_in, const int* in_sizes, int n_in,
                              void* d_out, int out_size) {
    const float* hs  = (const float*)d_in[0];
    const float* Wfc = (const float*)d_in[1];
    const float* bfc = (const float*)d_in[2];
    const float* Wpj = (const float*)d_in[3];
    const float* bpj = (const float*)d_in[4];
    float* out = (float*)d_out;

    void *pXs, *pAs, *pWs1, *pWs2, *pV;
    cudaGetSymbolAddress(&pXs,  g_Xs);
    cudaGetSymbolAddress(&pAs,  g_As);
    cudaGetSymbolAddress(&pWs1, g_Ws1);
    cudaGetSymbolAddress(&pWs2, g_Ws2);
    cudaGetSymbolAddress(&pV,   g_V);

    cudaFuncSetAttribute(gemm_fp16,
                         cudaFuncAttributeMaxDynamicSharedMemorySize, GEMM_SMEM);

    // Fork-join side stream (host-side objects; bounded, no device memory).
    cudaStream_t sB;
    cudaStreamCreateWithFlags(&sB, cudaStreamNonBlocking);
    cudaEvent_t evF, evW, evJ;
    cudaEventCreateWithFlags(&evF, cudaEventDisableTiming);
    cudaEventCreateWithFlags(&evW, cudaEventDisableTiming);
    cudaEventCreateWithFlags(&evJ, cudaEventDisableTiming);

    // ---- fork ----
    cudaEventRecord(evF, 0);
    cudaStreamWaitEvent(sB, evF, 0);

    // ---- stream B: W_proj convert (needed by gemm2), then attn_weights ----
    cvt_kernel<<<(DD * DD / 4 + 255) / 256, 256, 0, sB>>>(
        (const float4*)Wpj, (uint2*)pWs2, DD * DD / 4);
    cudaEventRecord(evW, sB);
    long long need = (long long)OUT1_ELEMS + (long long)ATTN_ELEMS;
    if ((long long)out_size >= need) {
        attnw_kernel<<<AWBLK, 256, 0, sB>>>(out + OUT1_ELEMS);
    }
    cudaEventRecord(evJ, sB);

    // ---- main chain (default stream) ----
    cvt_kernel<<<(OUT1_ELEMS / 4 + 255) / 256, 256>>>(
        (const float4*)hs, (uint2*)pXs, OUT1_ELEMS / 4);
    cvt_kernel<<<(DD * DD / 4 + 255) / 256, 256>>>(
        (const float4*)Wfc, (uint2*)pWs1, DD * DD / 4);

    gemm_fp16<<<dim3(DD / BN, MM / BM), 256, GEMM_SMEM>>>(
        (const __half*)pXs, (const __half*)pWs1, (float*)pV, bfc);

    scan_kernel<<<BB * HH * NCH, 128>>>();
    attn_out_kernel<<<BB * HH * NCH, 128>>>();

    cudaStreamWaitEvent(0, evW, 0);   // gemm2 needs W_proj fp16
    gemm_fp16<<<dim3(DD / BN, MM / BM), 256, GEMM_SMEM>>>(
        (const __half*)pAs, (const __half*)pWs2, out, bpj);

    // ---- join ----
    cudaStreamWaitEvent(0, evJ, 0);
}

// round 7
// speedup vs baseline: 1.0971x; 1.0372x over previous
#include <cuda_runtime.h>
#include <cuda_fp16.h>
#include <cstdint>

// ============================================================
// Problem constants
// ============================================================
#define BB 2
#define SS 2048
#define DD 1536
#define HH 12
#define HD 128
#define KK 1536                 // GEMM K (plain fp16)
#define MM 4096                 // BB * SS
#define OUT1_ELEMS (MM * DD)    // 6291456
#define ATTN_ELEMS (BB * HH * SS * SS)  // 100663296
#define NROWS (BB * HH * SS)    // 49152 attn_weights rows
#define QCH 256                 // q-chunk for prefix scan
#define NCH (SS / QCH)          // 8 chunks

// GEMM tiling
#define BM 128
#define BN 128
#define BK 32
#define STG 4
#define ROWB 80                  // smem row stride in bytes -- conflict-free ldmatrix
#define TILEB (128 * ROWB)       // 10240 bytes per A or B tile
#define STAGEB (2 * TILEB)       // 20480 bytes per stage
#define GEMM_SMEM (STG * STAGEB) // 81920

// nonzero-window writer: modest grid, low regs -> RF-compatible with GEMM
#define AWGRID 592               // ~4 CTAs/SM
#define AWWARPS (AWGRID * 8)     // warps total (256-thread CTAs)

// ============================================================
// Scratch (__device__ globals -- no allocation allowed)
// ============================================================
__device__ __half g_Xs[(size_t)MM * KK];   // fp16(hidden)
__device__ __half g_As[(size_t)MM * KK];   // fp16(attn out)
__device__ __half g_Ws1[(size_t)DD * KK];  // fp16(W_fc)
__device__ __half g_Ws2[(size_t)DD * KK];  // fp16(W_proj)
__device__ float  g_V[(size_t)MM * DD];    // fc output (value states)
__device__ float  g_P[(size_t)BB * HH * SS * HD];       // per-chunk local prefix
__device__ float  g_Ct[(size_t)BB * HH * NCH * HD];     // chunk totals

// ============================================================
// PTX helpers (sm_80-era instructions only: valid on compute_103)
// ============================================================
__device__ __forceinline__ uint32_t smem_to_u32(const void* p) {
    uint32_t a;
    asm("{ .reg .u64 t; cvta.to.shared.u64 t, %1; cvt.u32.u64 %0, t; }"
        : "=r"(a) : "l"(p));
    return a;
}

#define CP16(smem_u32, gptr) \
    asm volatile("cp.async.cg.shared.global [%0], [%1], 16;" \
        :: "r"(smem_u32), "l"(gptr))

#define CP_COMMIT() asm volatile("cp.async.commit_group;" ::: "memory")
#define CP_WAIT(n)  asm volatile("cp.async.wait_group %0;" :: "n"(n) : "memory")

__device__ __forceinline__ void ldsm_x4(uint32_t& r0, uint32_t& r1,
                                        uint32_t& r2, uint32_t& r3,
                                        uint32_t addr) {
    asm volatile("ldmatrix.sync.aligned.m8n8.x4.shared.b16 {%0,%1,%2,%3}, [%4];"
                 : "=r"(r0), "=r"(r1), "=r"(r2), "=r"(r3) : "r"(addr));
}

__device__ __forceinline__ void mma16816(float* c, const uint32_t* a,
                                         const uint32_t* b) {
    asm volatile(
        "mma.sync.aligned.m16n8k16.row.col.f32.f16.f16.f32 "
        "{%0,%1,%2,%3}, {%4,%5,%6,%7}, {%8,%9}, {%0,%1,%2,%3};"
        : "+f"(c[0]), "+f"(c[1]), "+f"(c[2]), "+f"(c[3])
        : "r"(a[0]), "r"(a[1]), "r"(a[2]), "r"(a[3]), "r"(b[0]), "r"(b[1]));
}

// ============================================================
// Kernel 1: fp32 -> fp16 convert (4 elements / thread)
// ============================================================
__global__ void __launch_bounds__(256)
cvt_kernel(const float4* __restrict__ src, uint2* __restrict__ dst, int n4) {
    int i = blockIdx.x * 256 + threadIdx.x;
    if (i >= n4) return;
    float4 v = src[i];
    __half2 p0 = __halves2half2(__float2half_rn(v.x), __float2half_rn(v.y));
    __half2 p1 = __halves2half2(__float2half_rn(v.z), __float2half_rn(v.w));
    uint2 o;
    o.x = *reinterpret_cast<uint32_t*>(&p0);
    o.y = *reinterpret_cast<uint32_t*>(&p1);
    dst[i] = o;
}

// ============================================================
// Kernel 2: fp16 mma.sync GEMM  C[M,1536] = A[M,KK] * B[1536,KK]^T + bias
// 128x128x32 CTA tile, 8 warps (2x4), 64x32 warp tile, 4-stage cp.async.
// ============================================================
__global__ void __launch_bounds__(256, 2)
gemm_fp16(const __half* __restrict__ A, const __half* __restrict__ Bw,
          float* __restrict__ C, const float* __restrict__ bias) {
    extern __shared__ char smem[];
    const uint32_t sb = smem_to_u32(smem);
    const int tid = threadIdx.x;
    const int lane = tid & 31;
    const int warp = tid >> 5;
    const int warpM = warp >> 2;   // 0..1 (64 rows each)
    const int warpN = warp & 3;    // 0..3 (32 cols each)

    const int ldRow = tid >> 1;
    const int ldCol = (tid & 1) * 2;
    const __half* gA = A + ((size_t)blockIdx.y * BM + ldRow) * KK + ldCol * 8;
    const __half* gB = Bw + ((size_t)blockIdx.x * BN + ldRow) * KK + ldCol * 8;
    const uint32_t stOff = (uint32_t)ldRow * ROWB + (uint32_t)ldCol * 16;

    const int aRow = (lane & 7) + ((lane >> 3) & 1) * 8;
    const uint32_t aBase = sb + (uint32_t)(warpM * 64 + aRow) * ROWB
                              + (uint32_t)(lane >> 4) * 16;
    const int bRow = (lane & 7) + ((lane >> 4) & 1) * 8;
    const uint32_t bBase = sb + TILEB + (uint32_t)(warpN * 32 + bRow) * ROWB
                              + (uint32_t)((lane >> 3) & 1) * 16;

    float acc[4][4][4];
#pragma unroll
    for (int i = 0; i < 4; ++i)
#pragma unroll
        for (int j = 0; j < 4; ++j)
#pragma unroll
            for (int k = 0; k < 4; ++k) acc[i][j][k] = 0.0f;

    const int NIT = KK / BK;  // 48

#pragma unroll
    for (int s = 0; s < STG - 1; ++s) {
        const uint32_t base = sb + s * STAGEB;
        const __half* ga = gA + s * BK;
        const __half* gb = gB + s * BK;
        CP16(base + stOff, ga);
        CP16(base + stOff + 16, ga + 8);
        CP16(base + TILEB + stOff, gb);
        CP16(base + TILEB + stOff + 16, gb + 8);
        CP_COMMIT();
    }

    for (int it = 0; it < NIT; ++it) {
        CP_WAIT(STG - 2);
        __syncthreads();

        const int pf = it + STG - 1;
        if (pf < NIT) {
            const uint32_t base = sb + (pf & (STG - 1)) * STAGEB;
            const __half* ga = gA + pf * BK;
            const __half* gb = gB + pf * BK;
            CP16(base + stOff, ga);
            CP16(base + stOff + 16, ga + 8);
            CP16(base + TILEB + stOff, gb);
            CP16(base + TILEB + stOff + 16, gb + 8);
        }
        CP_COMMIT();

        const uint32_t soff = (it & (STG - 1)) * STAGEB;
#pragma unroll
        for (int kk = 0; kk < 2; ++kk) {
            uint32_t a[4][4];
            uint32_t b[4][2];
#pragma unroll
            for (int mt = 0; mt < 4; ++mt)
                ldsm_x4(a[mt][0], a[mt][1], a[mt][2], a[mt][3],
                        aBase + soff + (uint32_t)mt * (16 * ROWB) + kk * 32);
            ldsm_x4(b[0][0], b[0][1], b[1][0], b[1][1],
                    bBase + soff + kk * 32);
            ldsm_x4(b[2][0], b[2][1], b[3][0], b[3][1],
                    bBase + soff + (16 * ROWB) + kk * 32);
#pragma unroll
            for (int mt = 0; mt < 4; ++mt)
#pragma unroll
                for (int nt = 0; nt < 4; ++nt)
                    mma16816(acc[mt][nt], a[mt], b[nt]);
        }
    }

    const int r0 = blockIdx.y * BM + warpM * 64 + (lane >> 2);
    const int c0 = blockIdx.x * BN + warpN * 32 + (lane & 3) * 2;
#pragma unroll
    for (int nt = 0; nt < 4; ++nt) {
        const int col = c0 + nt * 8;
        const float bx = bias[col], by = bias[col + 1];
#pragma unroll
        for (int mt = 0; mt < 4; ++mt) {
            const int row = r0 + mt * 16;
            float2 v0 = make_float2(acc[mt][nt][0] + bx, acc[mt][nt][1] + by);
            float2 v1 = make_float2(acc[mt][nt][2] + bx, acc[mt][nt][3] + by);
            *reinterpret_cast<float2*>(C + (size_t)row * DD + col) = v0;
            *reinterpret_cast<float2*>(C + (size_t)(row + 8) * DD + col) = v1;
        }
    }
}

// ============================================================
// Kernel 3a: per-chunk local prefix scan along q.
// ============================================================
__global__ void __launch_bounds__(128)
scan_kernel() {
    const int bhc = blockIdx.x;
    const int c = bhc & (NCH - 1);
    const int h = (bhc >> 3) % HH;
    const int b = bhc / (HH * NCH);
    const int d = threadIdx.x;

    const float* vp = g_V + ((size_t)b * SS + c * QCH) * DD + h * HD + d;
    float* pp = g_P + (((size_t)(b * HH + h) * SS) + c * QCH) * HD + d;

    float acc = 0.0f;
#pragma unroll 8
    for (int i = 0; i < QCH; ++i) {
        acc += vp[(size_t)i * DD];
        pp[(size_t)i * HD] = acc;
    }
    g_Ct[((size_t)(b * HH + h) * NCH + c) * HD + d] = acc;
}

// ============================================================
// Kernel 3b: window-mean from prefix sums -> fp16 into g_As.
// ============================================================
__global__ void __launch_bounds__(128)
attn_out_kernel() {
    const int bhc = blockIdx.x;
    const int c = bhc & (NCH - 1);
    const int h = (bhc >> 3) % HH;
    const int b = bhc / (HH * NCH);
    const int d = threadIdx.x;
    const int w = (1 << (h + 1)) - 1;
    const int q0 = c * QCH;
    const int c2a = (q0 - w) >> 8;       // arithmetic shift; may be negative

    const float* ct = g_Ct + (size_t)(b * HH + h) * NCH * HD + d;
    float run = 0.0f, offc = 0.0f, offA = 0.0f, offB = 0.0f;
#pragma unroll
    for (int cc = 0; cc < NCH; ++cc) {
        if (cc == c)       offc = run;
        if (cc == c2a)     offA = run;
        if (cc == c2a + 1) offB = run;
        run += ct[(size_t)cc * HD];
    }

    const float* Pb = g_P + (size_t)(b * HH + h) * SS * HD + d;
    __half* op = g_As + ((size_t)b * SS + q0) * KK + (size_t)h * HD + d;
    const float invw = 1.0f / (float)w;

#pragma unroll 4
    for (int i = 0; i < QCH; ++i) {
        const int q = q0 + i;
        const float Pq = Pb[(size_t)q * HD] + offc;
        const int q2 = q - w;
        float prev, inv;
        if (q2 >= 0) {
            const int cc2 = q2 >> 8;
            const float off2 = (cc2 == c2a) ? offA : offB;
            prev = Pb[(size_t)q2 * HD] + off2;
            inv = invw;
        } else {
            prev = 0.0f;
            inv = 1.0f / (float)(q + 1);
        }
        op[(size_t)i * KK] = __float2half_rn((Pq - prev) * inv);
    }
}

// ============================================================
// Kernel 4: attn_weights NONZERO window writer.
// Background zeros come from cudaMemsetAsync; this writes only the
// [q-w+1, q] segment of each row (~15% of bytes). One warp per row,
// grid-stride over rows. Low register use -> co-residency with GEMM.
// ============================================================
__global__ void __launch_bounds__(256)
attnw_nz_kernel(float* __restrict__ out2) {
    const int lane = threadIdx.x & 31;
    const int gw = blockIdx.x * 8 + (threadIdx.x >> 5);
    for (int row = gw; row < NROWS; row += AWWARPS) {
        const int q = row & (SS - 1);
        const int h = (row >> 11) % HH;
        const int w = (1 << (h + 1)) - 1;
        const int lo = (q - w + 1 > 0) ? (q - w + 1) : 0;
        const int len = (q + 1 < w) ? (q + 1) : w;
        const float inv = 1.0f / (float)len;
        float* p = out2 + (size_t)row * SS;
        for (int k = lo + lane; k <= q; k += 32)
            p[k] = inv;
    }
}

// ============================================================
// Host launcher -- memset + nz-writer on side stream, overlapped
// ============================================================
extern "C" void kernel_launch(void* const* d_in, const int* in_sizes, int n_in,
                              void* d_out, int out_size) {
    const float* hs  = (const float*)d_in[0];
    const float* Wfc = (const float*)d_in[1];
    const float* bfc = (const float*)d_in[2];
    const float* Wpj = (const float*)d_in[3];
    const float* bpj = (const float*)d_in[4];
    float* out = (float*)d_out;

    void *pXs, *pAs, *pWs1, *pWs2, *pV;
    cudaGetSymbolAddress(&pXs,  g_Xs);
    cudaGetSymbolAddress(&pAs,  g_As);
    cudaGetSymbolAddress(&pWs1, g_Ws1);
    cudaGetSymbolAddress(&pWs2, g_Ws2);
    cudaGetSymbolAddress(&pV,   g_V);

    cudaFuncSetAttribute(gemm_fp16,
                         cudaFuncAttributeMaxDynamicSharedMemorySize, GEMM_SMEM);

    // Fork-join side stream (host-side objects; bounded, no device memory).
    cudaStream_t sB;
    cudaStreamCreateWithFlags(&sB, cudaStreamNonBlocking);
    cudaEvent_t evF, evJ;
    cudaEventCreateWithFlags(&evF, cudaEventDisableTiming);
    cudaEventCreateWithFlags(&evJ, cudaEventDisableTiming);

    // ---- fork ----
    cudaEventRecord(evF, 0);
    cudaStreamWaitEvent(sB, evF, 0);

    // ---- stream B: zero-fill attn_weights, then write nonzero windows ----
    long long need = (long long)OUT1_ELEMS + (long long)ATTN_ELEMS;
    if ((long long)out_size >= need) {
        cudaMemsetAsync(out + OUT1_ELEMS, 0,
                        (size_t)ATTN_ELEMS * sizeof(float), sB);
        attnw_nz_kernel<<<AWGRID, 256, 0, sB>>>(out + OUT1_ELEMS);
    }
    cudaEventRecord(evJ, sB);

    // ---- main chain (default stream) ----
    cvt_kernel<<<(OUT1_ELEMS / 4 + 255) / 256, 256>>>(
        (const float4*)hs, (uint2*)pXs, OUT1_ELEMS / 4);
    cvt_kernel<<<(DD * DD / 4 + 255) / 256, 256>>>(
        (const float4*)Wfc, (uint2*)pWs1, DD * DD / 4);
    cvt_kernel<<<(DD * DD / 4 + 255) / 256, 256>>>(
        (const float4*)Wpj, (uint2*)pWs2, DD * DD / 4);

    gemm_fp16<<<dim3(DD / BN, MM / BM), 256, GEMM_SMEM>>>(
        (const __half*)pXs, (const __half*)pWs1, (float*)pV, bfc);

    scan_kernel<<<BB * HH * NCH, 128>>>();
    attn_out_kernel<<<BB * HH * NCH, 128>>>();

    gemm_fp16<<<dim3(DD / BN, MM / BM), 256, GEMM_SMEM>>>(
        (const __half*)pAs, (const __half*)pWs2, out, bpj);

    // ---- join ----
    cudaStreamWaitEvent(0, evJ, 0);
}

// round 8
// speedup vs baseline: 1.1248x; 1.0253x over previous
#include <cuda_runtime.h>
#include <cuda_fp16.h>
#include <cstdint>

// ============================================================
// Problem constants
// ============================================================
#define BB 2
#define SS 2048
#define DD 1536
#define HH 12
#define HD 128
#define KK 1536                 // GEMM K (plain fp16)
#define MM 4096                 // BB * SS
#define OUT1_ELEMS (MM * DD)    // 6291456
#define ATTN_ELEMS (BB * HH * SS * SS)  // 100663296
#define NROWS (BB * HH * SS)    // 49152 attn_weights rows
#define QCH 256                 // q-chunk for prefix scan
#define NCH (SS / QCH)          // 8 chunks

// GEMM tiling
#define BM 128
#define BN 128
#define BK 32
#define STG 4
#define ROWB 80                  // smem row stride in bytes -- conflict-free ldmatrix
#define TILEB (128 * ROWB)       // 10240 bytes per A or B tile
#define STAGEB (2 * TILEB)       // 20480 bytes per stage
#define GEMM_SMEM (STG * STAGEB) // 81920
#define NTILES ((DD / BN) * (MM / BM))   // 384 GEMM CTAs

// attn_weights writer CTAs fused into the GEMM launch (scheduled FIRST)
#define AWC 148                  // ~1 writer CTA per SM, co-resident with GEMM

// ============================================================
// Scratch (__device__ globals -- no allocation allowed)
// ============================================================
__device__ __half g_Xs[(size_t)MM * KK];   // fp16(hidden)
__device__ __half g_As[(size_t)MM * KK];   // fp16(attn out)
__device__ __half g_Ws1[(size_t)DD * KK];  // fp16(W_fc)
__device__ __half g_Ws2[(size_t)DD * KK];  // fp16(W_proj)
__device__ float  g_V[(size_t)MM * DD];    // fc output (value states)
__device__ float  g_P[(size_t)BB * HH * SS * HD];       // per-chunk local prefix
__device__ float  g_Ct[(size_t)BB * HH * NCH * HD];     // chunk totals

// ============================================================
// PTX helpers (sm_80-era instructions only: valid on compute_103)
// ============================================================
__device__ __forceinline__ uint32_t smem_to_u32(const void* p) {
    uint32_t a;
    asm("{ .reg .u64 t; cvta.to.shared.u64 t, %1; cvt.u32.u64 %0, t; }"
        : "=r"(a) : "l"(p));
    return a;
}

#define CP16(smem_u32, gptr) \
    asm volatile("cp.async.cg.shared.global [%0], [%1], 16;" \
        :: "r"(smem_u32), "l"(gptr))

#define CP_COMMIT() asm volatile("cp.async.commit_group;" ::: "memory")
#define CP_WAIT(n)  asm volatile("cp.async.wait_group %0;" :: "n"(n) : "memory")

__device__ __forceinline__ void ldsm_x4(uint32_t& r0, uint32_t& r1,
                                        uint32_t& r2, uint32_t& r3,
                                        uint32_t addr) {
    asm volatile("ldmatrix.sync.aligned.m8n8.x4.shared.b16 {%0,%1,%2,%3}, [%4];"
                 : "=r"(r0), "=r"(r1), "=r"(r2), "=r"(r3) : "r"(addr));
}

__device__ __forceinline__ void mma16816(float* c, const uint32_t* a,
                                         const uint32_t* b) {
    asm volatile(
        "mma.sync.aligned.m16n8k16.row.col.f32.f16.f16.f32 "
        "{%0,%1,%2,%3}, {%4,%5,%6,%7}, {%8,%9}, {%0,%1,%2,%3};"
        : "+f"(c[0]), "+f"(c[1]), "+f"(c[2]), "+f"(c[3])
        : "r"(a[0]), "r"(a[1]), "r"(a[2]), "r"(a[3]), "r"(b[0]), "r"(b[1]));
}

// ============================================================
// Kernel 1: fp32 -> fp16 convert (4 elements / thread)
// ============================================================
__global__ void __launch_bounds__(256)
cvt_kernel(const float4* __restrict__ src, uint2* __restrict__ dst, int n4) {
    int i = blockIdx.x * 256 + threadIdx.x;
    if (i >= n4) return;
    float4 v = src[i];
    __half2 p0 = __halves2half2(__float2half_rn(v.x), __float2half_rn(v.y));
    __half2 p1 = __halves2half2(__float2half_rn(v.z), __float2half_rn(v.w));
    uint2 o;
    o.x = *reinterpret_cast<uint32_t*>(&p0);
    o.y = *reinterpret_cast<uint32_t*>(&p1);
    dst[i] = o;
}

// ============================================================
// Kernel 2: FUSED fp16 GEMM + attn_weights row writer.
// blockIdx.x <  AWC           : writer CTA (streaming stores, rows [awR0,awR1))
// blockIdx.x >= AWC           : GEMM CTA (identical 128x128x32 pipeline)
// Writer CTAs carry low indices so they become resident FIRST and stay
// co-resident with GEMM CTAs for the whole launch (intra-kernel overlap --
// the graph/stream path proved serial in R5/R7).
// ============================================================
__global__ void __launch_bounds__(256, 2)
gemm_fp16_aw(const __half* __restrict__ A, const __half* __restrict__ Bw,
             float* __restrict__ C, const float* __restrict__ bias,
             float* __restrict__ aw, int awR0, int awR1) {
    // ---------------- writer role ----------------
    if (blockIdx.x < AWC) {
        if (aw == nullptr) return;
        const int k0 = threadIdx.x * 8;
        for (int row = awR0 + blockIdx.x; row < awR1; row += AWC) {
            const int q = row & (SS - 1);
            const int h = (row >> 11) % HH;
            const int w = (1 << (h + 1)) - 1;
            const int lo = q - w + 1;
            const int len = (q + 1 < w) ? (q + 1) : w;
            const float inv = 1.0f / (float)len;
            float* p = aw + (size_t)row * SS;
            float4 v0, v1;
            int k;
            k = k0 + 0; v0.x = (k <= q && k >= lo) ? inv : 0.0f;
            k = k0 + 1; v0.y = (k <= q && k >= lo) ? inv : 0.0f;
            k = k0 + 2; v0.z = (k <= q && k >= lo) ? inv : 0.0f;
            k = k0 + 3; v0.w = (k <= q && k >= lo) ? inv : 0.0f;
            k = k0 + 4; v1.x = (k <= q && k >= lo) ? inv : 0.0f;
            k = k0 + 5; v1.y = (k <= q && k >= lo) ? inv : 0.0f;
            k = k0 + 6; v1.z = (k <= q && k >= lo) ? inv : 0.0f;
            k = k0 + 7; v1.w = (k <= q && k >= lo) ? inv : 0.0f;
            __stcs(reinterpret_cast<float4*>(p + k0), v0);
            __stcs(reinterpret_cast<float4*>(p + k0 + 4), v1);
        }
        return;
    }

    // ---------------- GEMM role ----------------
    const int bxy = blockIdx.x - AWC;
    const int bx = bxy % (DD / BN);   // N tile
    const int by = bxy / (DD / BN);   // M tile

    extern __shared__ char smem[];
    const uint32_t sb = smem_to_u32(smem);
    const int tid = threadIdx.x;
    const int lane = tid & 31;
    const int warp = tid >> 5;
    const int warpM = warp >> 2;   // 0..1 (64 rows each)
    const int warpN = warp & 3;    // 0..3 (32 cols each)

    const int ldRow = tid >> 1;
    const int ldCol = (tid & 1) * 2;
    const __half* gA = A + ((size_t)by * BM + ldRow) * KK + ldCol * 8;
    const __half* gB = Bw + ((size_t)bx * BN + ldRow) * KK + ldCol * 8;
    const uint32_t stOff = (uint32_t)ldRow * ROWB + (uint32_t)ldCol * 16;

    const int aRow = (lane & 7) + ((lane >> 3) & 1) * 8;
    const uint32_t aBase = sb + (uint32_t)(warpM * 64 + aRow) * ROWB
                              + (uint32_t)(lane >> 4) * 16;
    const int bRow = (lane & 7) + ((lane >> 4) & 1) * 8;
    const uint32_t bBase = sb + TILEB + (uint32_t)(warpN * 32 + bRow) * ROWB
                              + (uint32_t)((lane >> 3) & 1) * 16;

    float acc[4][4][4];
#pragma unroll
    for (int i = 0; i < 4; ++i)
#pragma unroll
        for (int j = 0; j < 4; ++j)
#pragma unroll
            for (int k = 0; k < 4; ++k) acc[i][j][k] = 0.0f;

    const int NIT = KK / BK;  // 48

#pragma unroll
    for (int s = 0; s < STG - 1; ++s) {
        const uint32_t base = sb + s * STAGEB;
        const __half* ga = gA + s * BK;
        const __half* gb = gB + s * BK;
        CP16(base + stOff, ga);
        CP16(base + stOff + 16, ga + 8);
        CP16(base + TILEB + stOff, gb);
        CP16(base + TILEB + stOff + 16, gb + 8);
        CP_COMMIT();
    }

    for (int it = 0; it < NIT; ++it) {
        CP_WAIT(STG - 2);
        __syncthreads();

        const int pf = it + STG - 1;
        if (pf < NIT) {
            const uint32_t base = sb + (pf & (STG - 1)) * STAGEB;
            const __half* ga = gA + pf * BK;
            const __half* gb = gB + pf * BK;
            CP16(base + stOff, ga);
            CP16(base + stOff + 16, ga + 8);
            CP16(base + TILEB + stOff, gb);
            CP16(base + TILEB + stOff + 16, gb + 8);
        }
        CP_COMMIT();

        const uint32_t soff = (it & (STG - 1)) * STAGEB;
#pragma unroll
        for (int kk = 0; kk < 2; ++kk) {
            uint32_t a[4][4];
            uint32_t b[4][2];
#pragma unroll
            for (int mt = 0; mt < 4; ++mt)
                ldsm_x4(a[mt][0], a[mt][1], a[mt][2], a[mt][3],
                        aBase + soff + (uint32_t)mt * (16 * ROWB) + kk * 32);
            ldsm_x4(b[0][0], b[0][1], b[1][0], b[1][1],
                    bBase + soff + kk * 32);
            ldsm_x4(b[2][0], b[2][1], b[3][0], b[3][1],
                    bBase + soff + (16 * ROWB) + kk * 32);
#pragma unroll
            for (int mt = 0; mt < 4; ++mt)
#pragma unroll
                for (int nt = 0; nt < 4; ++nt)
                    mma16816(acc[mt][nt], a[mt], b[nt]);
        }
    }

    const int r0 = by * BM + warpM * 64 + (lane >> 2);
    const int c0 = bx * BN + warpN * 32 + (lane & 3) * 2;
#pragma unroll
    for (int nt = 0; nt < 4; ++nt) {
        const int col = c0 + nt * 8;
        const float bx2 = bias[col], by2 = bias[col + 1];
#pragma unroll
        for (int mt = 0; mt < 4; ++mt) {
            const int row = r0 + mt * 16;
            float2 v0 = make_float2(acc[mt][nt][0] + bx2, acc[mt][nt][1] + by2);
            float2 v1 = make_float2(acc[mt][nt][2] + bx2, acc[mt][nt][3] + by2);
            *reinterpret_cast<float2*>(C + (size_t)row * DD + col) = v0;
            *reinterpret_cast<float2*>(C + (size_t)(row + 8) * DD + col) = v1;
        }
    }
}

// ============================================================
// Kernel 3a: per-chunk local prefix scan along q.
// ============================================================
__global__ void __launch_bounds__(128)
scan_kernel() {
    const int bhc = blockIdx.x;
    const int c = bhc & (NCH - 1);
    const int h = (bhc >> 3) % HH;
    const int b = bhc / (HH * NCH);
    const int d = threadIdx.x;

    const float* vp = g_V + ((size_t)b * SS + c * QCH) * DD + h * HD + d;
    float* pp = g_P + (((size_t)(b * HH + h) * SS) + c * QCH) * HD + d;

    float acc = 0.0f;
#pragma unroll 8
    for (int i = 0; i < QCH; ++i) {
        acc += vp[(size_t)i * DD];
        pp[(size_t)i * HD] = acc;
    }
    g_Ct[((size_t)(b * HH + h) * NCH + c) * HD + d] = acc;
}

// ============================================================
// Kernel 3b: window-mean from prefix sums -> fp16 into g_As.
// ============================================================
__global__ void __launch_bounds__(128)
attn_out_kernel() {
    const int bhc = blockIdx.x;
    const int c = bhc & (NCH - 1);
    const int h = (bhc >> 3) % HH;
    const int b = bhc / (HH * NCH);
    const int d = threadIdx.x;
    const int w = (1 << (h + 1)) - 1;
    const int q0 = c * QCH;
    const int c2a = (q0 - w) >> 8;       // arithmetic shift; may be negative

    const float* ct = g_Ct + (size_t)(b * HH + h) * NCH * HD + d;
    float run = 0.0f, offc = 0.0f, offA = 0.0f, offB = 0.0f;
#pragma unroll
    for (int cc = 0; cc < NCH; ++cc) {
        if (cc == c)       offc = run;
        if (cc == c2a)     offA = run;
        if (cc == c2a + 1) offB = run;
        run += ct[(size_t)cc * HD];
    }

    const float* Pb = g_P + (size_t)(b * HH + h) * SS * HD + d;
    __half* op = g_As + ((size_t)b * SS + q0) * KK + (size_t)h * HD + d;
    const float invw = 1.0f / (float)w;

#pragma unroll 4
    for (int i = 0; i < QCH; ++i) {
        const int q = q0 + i;
        const float Pq = Pb[(size_t)q * HD] + offc;
        const int q2 = q - w;
        float prev, inv;
        if (q2 >= 0) {
            const int cc2 = q2 >> 8;
            const float off2 = (cc2 == c2a) ? offA : offB;
            prev = Pb[(size_t)q2 * HD] + off2;
            inv = invw;
        } else {
            prev = 0.0f;
            inv = 1.0f / (float)(q + 1);
        }
        op[(size_t)i * KK] = __float2half_rn((Pq - prev) * inv);
    }
}

// ============================================================
// Host launcher -- single stream; overlap happens INSIDE the fused kernels
// ============================================================
extern "C" void kernel_launch(void* const* d_in, const int* in_sizes, int n_in,
                              void* d_out, int out_size) {
    const float* hs  = (const float*)d_in[0];
    const float* Wfc = (const float*)d_in[1];
    const float* bfc = (const float*)d_in[2];
    const float* Wpj = (const float*)d_in[3];
    const float* bpj = (const float*)d_in[4];
    float* out = (float*)d_out;

    void *pXs, *pAs, *pWs1, *pWs2, *pV;
    cudaGetSymbolAddress(&pXs,  g_Xs);
    cudaGetSymbolAddress(&pAs,  g_As);
    cudaGetSymbolAddress(&pWs1, g_Ws1);
    cudaGetSymbolAddress(&pWs2, g_Ws2);
    cudaGetSymbolAddress(&pV,   g_V);

    cudaFuncSetAttribute(gemm_fp16_aw,
                         cudaFuncAttributeMaxDynamicSharedMemorySize, GEMM_SMEM);

    long long need = (long long)OUT1_ELEMS + (long long)ATTN_ELEMS;
    float* aw = ((long long)out_size >= need) ? (out + OUT1_ELEMS) : nullptr;

    // 1) fp32 -> fp16 converts
    cvt_kernel<<<(OUT1_ELEMS / 4 + 255) / 256, 256>>>(
        (const float4*)hs, (uint2*)pXs, OUT1_ELEMS / 4);
    cvt_kernel<<<(DD * DD / 4 + 255) / 256, 256>>>(
        (const float4*)Wfc, (uint2*)pWs1, DD * DD / 4);
    cvt_kernel<<<(DD * DD / 4 + 255) / 256, 256>>>(
        (const float4*)Wpj, (uint2*)pWs2, DD * DD / 4);

    // 2) V = X @ W_fc^T + b_fc   (+ first half of attn_weights rows)
    gemm_fp16_aw<<<AWC + NTILES, 256, GEMM_SMEM>>>(
        (const __half*)pXs, (const __half*)pWs1, (float*)pV, bfc,
        aw, 0, NROWS / 2);

    // 3) window-mean attention via chunked prefix sums -> g_As (fp16)
    scan_kernel<<<BB * HH * NCH, 128>>>();
    attn_out_kernel<<<BB * HH * NCH, 128>>>();

    // 4) out = attn_out @ W_proj^T + b_proj  (+ second half of attn_weights)
    gemm_fp16_aw<<<AWC + NTILES, 256, GEMM_SMEM>>>(
        (const __half*)pAs, (const __half*)pWs2, out, bpj,
        aw, NROWS / 2, NROWS);
}

// round 9
// speedup vs baseline: 1.1277x; 1.0025x over previous
#include <cuda_runtime.h>
#include <cuda_fp16.h>
#include <cstdint>

// ============================================================
// Problem constants
// ============================================================
#define BB 2
#define SS 2048
#define DD 1536
#define HH 12
#define HD 128
#define KK 1536                 // GEMM K (plain fp16)
#define MM 4096                 // BB * SS
#define OUT1_ELEMS (MM * DD)    // 6291456
#define ATTN_ELEMS (BB * HH * SS * SS)  // 100663296
#define NROWS (BB * HH * SS)    // 49152 attn_weights rows
#define QCH 256                 // q-chunk for prefix scan
#define NCH (SS / QCH)          // 8 chunks

// GEMM tiling
#define BM 128
#define BN 128
#define BK 32
#define STG 4
#define ROWB 80                  // smem row stride in bytes -- conflict-free ldmatrix
#define TILEB (128 * ROWB)       // 10240 bytes per A or B tile
#define STAGEB (2 * TILEB)       // 20480 bytes per stage
#define GEMM_SMEM (STG * STAGEB) // 81920
#define NTILES ((DD / BN) * (MM / BM))   // 384 GEMM CTAs

// attn_weights writer CTAs fused into the GEMM launch (scheduled FIRST)
#define AWC 148                  // ~1 writer CTA per SM, co-resident with GEMM

// ============================================================
// Scratch (__device__ globals -- no allocation allowed)
// ============================================================
__device__ __half g_Xs[(size_t)MM * KK];   // fp16(hidden)
__device__ __half g_As[(size_t)MM * KK];   // fp16(attn out)
__device__ __half g_Ws1[(size_t)DD * KK];  // fp16(W_fc)
__device__ __half g_Ws2[(size_t)DD * KK];  // fp16(W_proj)
__device__ float  g_V[(size_t)MM * DD];    // fc output (value states)
__device__ float  g_P[(size_t)BB * HH * SS * HD];       // per-chunk local prefix

// ============================================================
// PTX helpers (sm_80-era instructions only: valid on compute_103)
// ============================================================
__device__ __forceinline__ uint32_t smem_to_u32(const void* p) {
    uint32_t a;
    asm("{ .reg .u64 t; cvta.to.shared.u64 t, %1; cvt.u32.u64 %0, t; }"
        : "=r"(a) : "l"(p));
    return a;
}

#define CP16(smem_u32, gptr) \
    asm volatile("cp.async.cg.shared.global [%0], [%1], 16;" \
        :: "r"(smem_u32), "l"(gptr))

#define CP_COMMIT() asm volatile("cp.async.commit_group;" ::: "memory")
#define CP_WAIT(n)  asm volatile("cp.async.wait_group %0;" :: "n"(n) : "memory")

__device__ __forceinline__ void ldsm_x4(uint32_t& r0, uint32_t& r1,
                                        uint32_t& r2, uint32_t& r3,
                                        uint32_t addr) {
    asm volatile("ldmatrix.sync.aligned.m8n8.x4.shared.b16 {%0,%1,%2,%3}, [%4];"
                 : "=r"(r0), "=r"(r1), "=r"(r2), "=r"(r3) : "r"(addr));
}

__device__ __forceinline__ void mma16816(float* c, const uint32_t* a,
                                         const uint32_t* b) {
    asm volatile(
        "mma.sync.aligned.m16n8k16.row.col.f32.f16.f16.f32 "
        "{%0,%1,%2,%3}, {%4,%5,%6,%7}, {%8,%9}, {%0,%1,%2,%3};"
        : "+f"(c[0]), "+f"(c[1]), "+f"(c[2]), "+f"(c[3])
        : "r"(a[0]), "r"(a[1]), "r"(a[2]), "r"(a[3]), "r"(b[0]), "r"(b[1]));
}

// ============================================================
// Kernel 1: fp32 -> fp16 convert (4 elements / thread)
// ============================================================
__global__ void __launch_bounds__(256)
cvt_kernel(const float4* __restrict__ src, uint2* __restrict__ dst, int n4) {
    int i = blockIdx.x * 256 + threadIdx.x;
    if (i >= n4) return;
    float4 v = src[i];
    __half2 p0 = __halves2half2(__float2half_rn(v.x), __float2half_rn(v.y));
    __half2 p1 = __halves2half2(__float2half_rn(v.z), __float2half_rn(v.w));
    uint2 o;
    o.x = *reinterpret_cast<uint32_t*>(&p0);
    o.y = *reinterpret_cast<uint32_t*>(&p1);
    dst[i] = o;
}

// ============================================================
// Kernel 2: FUSED fp16 GEMM + attn_weights row writer.
// blockIdx.x <  AWC : writer CTA (streaming stores, rows [awR0,awR1))
// blockIdx.x >= AWC : GEMM CTA (128x128x32 pipeline)
// ============================================================
__global__ void __launch_bounds__(256, 2)
gemm_fp16_aw(const __half* __restrict__ A, const __half* __restrict__ Bw,
             float* __restrict__ C, const float* __restrict__ bias,
             float* __restrict__ aw, int awR0, int awR1) {
    // ---------------- writer role ----------------
    if (blockIdx.x < AWC) {
        if (aw == nullptr) return;
        const int k0 = threadIdx.x * 8;
        for (int row = awR0 + blockIdx.x; row < awR1; row += AWC) {
            const int q = row & (SS - 1);
            const int h = (row >> 11) % HH;
            const int w = (1 << (h + 1)) - 1;
            const int lo = q - w + 1;
            const int len = (q + 1 < w) ? (q + 1) : w;
            const float inv = 1.0f / (float)len;
            float* p = aw + (size_t)row * SS;
            float4 v0, v1;
            int k;
            k = k0 + 0; v0.x = (k <= q && k >= lo) ? inv : 0.0f;
            k = k0 + 1; v0.y = (k <= q && k >= lo) ? inv : 0.0f;
            k = k0 + 2; v0.z = (k <= q && k >= lo) ? inv : 0.0f;
            k = k0 + 3; v0.w = (k <= q && k >= lo) ? inv : 0.0f;
            k = k0 + 4; v1.x = (k <= q && k >= lo) ? inv : 0.0f;
            k = k0 + 5; v1.y = (k <= q && k >= lo) ? inv : 0.0f;
            k = k0 + 6; v1.z = (k <= q && k >= lo) ? inv : 0.0f;
            k = k0 + 7; v1.w = (k <= q && k >= lo) ? inv : 0.0f;
            __stcs(reinterpret_cast<float4*>(p + k0), v0);
            __stcs(reinterpret_cast<float4*>(p + k0 + 4), v1);
        }
        return;
    }

    // ---------------- GEMM role ----------------
    const int bxy = blockIdx.x - AWC;
    const int bx = bxy % (DD / BN);   // N tile
    const int by = bxy / (DD / BN);   // M tile

    extern __shared__ char smem[];
    const uint32_t sb = smem_to_u32(smem);
    const int tid = threadIdx.x;
    const int lane = tid & 31;
    const int warp = tid >> 5;
    const int warpM = warp >> 2;   // 0..1 (64 rows each)
    const int warpN = warp & 3;    // 0..3 (32 cols each)

    const int ldRow = tid >> 1;
    const int ldCol = (tid & 1) * 2;
    const __half* gA = A + ((size_t)by * BM + ldRow) * KK + ldCol * 8;
    const __half* gB = Bw + ((size_t)bx * BN + ldRow) * KK + ldCol * 8;
    const uint32_t stOff = (uint32_t)ldRow * ROWB + (uint32_t)ldCol * 16;

    const int aRow = (lane & 7) + ((lane >> 3) & 1) * 8;
    const uint32_t aBase = sb + (uint32_t)(warpM * 64 + aRow) * ROWB
                              + (uint32_t)(lane >> 4) * 16;
    const int bRow = (lane & 7) + ((lane >> 4) & 1) * 8;
    const uint32_t bBase = sb + TILEB + (uint32_t)(warpN * 32 + bRow) * ROWB
                              + (uint32_t)((lane >> 3) & 1) * 16;

    float acc[4][4][4];
#pragma unroll
    for (int i = 0; i < 4; ++i)
#pragma unroll
        for (int j = 0; j < 4; ++j)
#pragma unroll
            for (int k = 0; k < 4; ++k) acc[i][j][k] = 0.0f;

    const int NIT = KK / BK;  // 48

#pragma unroll
    for (int s = 0; s < STG - 1; ++s) {
        const uint32_t base = sb + s * STAGEB;
        const __half* ga = gA + s * BK;
        const __half* gb = gB + s * BK;
        CP16(base + stOff, ga);
        CP16(base + stOff + 16, ga + 8);
        CP16(base + TILEB + stOff, gb);
        CP16(base + TILEB + stOff + 16, gb + 8);
        CP_COMMIT();
    }

    for (int it = 0; it < NIT; ++it) {
        CP_WAIT(STG - 2);
        __syncthreads();

        const int pf = it + STG - 1;
        if (pf < NIT) {
            const uint32_t base = sb + (pf & (STG - 1)) * STAGEB;
            const __half* ga = gA + pf * BK;
            const __half* gb = gB + pf * BK;
            CP16(base + stOff, ga);
            CP16(base + stOff + 16, ga + 8);
            CP16(base + TILEB + stOff, gb);
            CP16(base + TILEB + stOff + 16, gb + 8);
        }
        CP_COMMIT();

        const uint32_t soff = (it & (STG - 1)) * STAGEB;
#pragma unroll
        for (int kk = 0; kk < 2; ++kk) {
            uint32_t a[4][4];
            uint32_t b[4][2];
#pragma unroll
            for (int mt = 0; mt < 4; ++mt)
                ldsm_x4(a[mt][0], a[mt][1], a[mt][2], a[mt][3],
                        aBase + soff + (uint32_t)mt * (16 * ROWB) + kk * 32);
            ldsm_x4(b[0][0], b[0][1], b[1][0], b[1][1],
                    bBase + soff + kk * 32);
            ldsm_x4(b[2][0], b[2][1], b[3][0], b[3][1],
                    bBase + soff + (16 * ROWB) + kk * 32);
#pragma unroll
            for (int mt = 0; mt < 4; ++mt)
#pragma unroll
                for (int nt = 0; nt < 4; ++nt)
                    mma16816(acc[mt][nt], a[mt], b[nt]);
        }
    }

    const int r0 = by * BM + warpM * 64 + (lane >> 2);
    const int c0 = bx * BN + warpN * 32 + (lane & 3) * 2;
#pragma unroll
    for (int nt = 0; nt < 4; ++nt) {
        const int col = c0 + nt * 8;
        const float bx2 = bias[col], by2 = bias[col + 1];
#pragma unroll
        for (int mt = 0; mt < 4; ++mt) {
            const int row = r0 + mt * 16;
            float2 v0 = make_float2(acc[mt][nt][0] + bx2, acc[mt][nt][1] + by2);
            float2 v1 = make_float2(acc[mt][nt][2] + bx2, acc[mt][nt][3] + by2);
            *reinterpret_cast<float2*>(C + (size_t)row * DD + col) = v0;
            *reinterpret_cast<float2*>(C + (size_t)(row + 8) * DD + col) = v1;
        }
    }
}

// ============================================================
// Kernel 3: FUSED window-mean attention (scan + output in one kernel).
// Grid: B*H*2 = 48 CTAs, 512 threads = (chunk c in 0..7) x (d-half 0..63).
// Phase 1: per-thread serial scan of its 256-q chunk -> g_P + smem totals.
// Phase 2: chunk-offset prefix from smem (same add order as before).
// Phase 3: out[q] = (P[q]-P[q-w])/len -> fp16 into g_As (L1/L2-hot reads).
// ============================================================
__global__ void __launch_bounds__(512)
attn_fused_kernel() {
    __shared__ float tot[NCH][64 + 1];

    const int half = blockIdx.x & 1;
    const int bh = blockIdx.x >> 1;
    const int b = bh / HH;
    const int h = bh % HH;
    const int c = threadIdx.x >> 6;          // 0..7
    const int dl = threadIdx.x & 63;
    const int d = half * 64 + dl;
    const int w = (1 << (h + 1)) - 1;
    const int q0 = c * QCH;

    // Phase 1: local inclusive scan of chunk c for column d
    const float* vp = g_V + ((size_t)b * SS + q0) * DD + h * HD + d;
    float* pp = g_P + ((size_t)(b * HH + h) * SS + q0) * HD + d;
    float acc = 0.0f;
#pragma unroll 8
    for (int i = 0; i < QCH; ++i) {
        acc += vp[(size_t)i * DD];
        pp[(size_t)i * HD] = acc;
    }
    tot[c][dl] = acc;
    __syncthreads();

    // Phase 2: exclusive chunk offsets (same accumulation order as R4-R8)
    const int c2a = (q0 - w) >> 8;           // arithmetic shift; may be negative
    float run = 0.0f, offc = 0.0f, offA = 0.0f, offB = 0.0f;
#pragma unroll
    for (int cc = 0; cc < NCH; ++cc) {
        if (cc == c)       offc = run;
        if (cc == c2a)     offA = run;
        if (cc == c2a + 1) offB = run;
        run += tot[cc][dl];
    }

    // Phase 3: window mean -> fp16
    const float* Pb = g_P + (size_t)(b * HH + h) * SS * HD + d;
    __half* op = g_As + ((size_t)b * SS + q0) * KK + (size_t)h * HD + d;
    const float invw = 1.0f / (float)w;
#pragma unroll 4
    for (int i = 0; i < QCH; ++i) {
        const int q = q0 + i;
        const float Pq = Pb[(size_t)q * HD] + offc;
        const int q2 = q - w;
        float prev, inv;
        if (q2 >= 0) {
            const int cc2 = q2 >> 8;
            const float off2 = (cc2 == c2a) ? offA : offB;
            prev = Pb[(size_t)q2 * HD] + off2;
            inv = invw;
        } else {
            prev = 0.0f;
            inv = 1.0f / (float)(q + 1);
        }
        op[(size_t)i * KK] = __float2half_rn((Pq - prev) * inv);
    }
}

// ============================================================
// Host launcher -- single stream; overlap happens INSIDE the fused kernels
// ============================================================
extern "C" void kernel_launch(void* const* d_in, const int* in_sizes, int n_in,
                              void* d_out, int out_size) {
    const float* hs  = (const float*)d_in[0];
    const float* Wfc = (const float*)d_in[1];
    const float* bfc = (const float*)d_in[2];
    const float* Wpj = (const float*)d_in[3];
    const float* bpj = (const float*)d_in[4];
    float* out = (float*)d_out;

    void *pXs, *pAs, *pWs1, *pWs2, *pV;
    cudaGetSymbolAddress(&pXs,  g_Xs);
    cudaGetSymbolAddress(&pAs,  g_As);
    cudaGetSymbolAddress(&pWs1, g_Ws1);
    cudaGetSymbolAddress(&pWs2, g_Ws2);
    cudaGetSymbolAddress(&pV,   g_V);

    cudaFuncSetAttribute(gemm_fp16_aw,
                         cudaFuncAttributeMaxDynamicSharedMemorySize, GEMM_SMEM);

    long long need = (long long)OUT1_ELEMS + (long long)ATTN_ELEMS;
    float* aw = ((long long)out_size >= need) ? (out + OUT1_ELEMS) : nullptr;

    // 1) fp32 -> fp16 converts
    cvt_kernel<<<(OUT1_ELEMS / 4 + 255) / 256, 256>>>(
        (const float4*)hs, (uint2*)pXs, OUT1_ELEMS / 4);
    cvt_kernel<<<(DD * DD / 4 + 255) / 256, 256>>>(
        (const float4*)Wfc, (uint2*)pWs1, DD * DD / 4);
    cvt_kernel<<<(DD * DD / 4 + 255) / 256, 256>>>(
        (const float4*)Wpj, (uint2*)pWs2, DD * DD / 4);

    // 2) V = X @ W_fc^T + b_fc   (+ first half of attn_weights rows)
    gemm_fp16_aw<<<AWC + NTILES, 256, GEMM_SMEM>>>(
        (const __half*)pXs, (const __half*)pWs1, (float*)pV, bfc,
        aw, 0, NROWS / 2);

    // 3) fused window-mean attention -> g_As (fp16)
    attn_fused_kernel<<<BB * HH * 2, 512>>>();

    // 4) out = attn_out @ W_proj^T + b_proj  (+ second half of attn_weights)
    gemm_fp16_aw<<<AWC + NTILES, 256, GEMM_SMEM>>>(
        (const __half*)pAs, (const __half*)pWs2, out, bpj,
        aw, NROWS / 2, NROWS);
}